// round 1
// baseline (speedup 1.0000x reference)
#include <cuda_runtime.h>
#include <cuda_bf16.h>
#include <cstdint>

// Problem constants
#define NPTS 32768   // candidate points per side
#define MQ   8192    // query (shortcut) points per side
#define CF   256     // feature channels
#define NSLICE 8     // candidate slices (stride interleave)
#define TILE_P 64    // candidate PAIRS per tile per slice (=128 candidates)
#define NPAIR  (NPTS / (2 * NSLICE))          // 2048 pairs per slice
#define NTILE  (NPAIR / TILE_P)               // 32 tiles

// Scratch: packed candidates, layout [side][slice][pair][2] float4
//   float4 A = (x0, x1, y0, y1),  float4 B = (z0, z1, w0, w1)  with w = |b|^2
// candidate j0 = (2*pair)*NSLICE + slice, j1 = j0 + NSLICE
__device__ float4 g_pack[2][NSLICE][NPAIR][2];
__device__ int    g_idx2[2][MQ];

// ---------------- f32x2 helpers ----------------
__device__ __forceinline__ unsigned long long pack2(float a, float b) {
    unsigned long long r;
    asm("mov.b64 %0, {%1, %2};" : "=l"(r) : "f"(a), "f"(b));
    return r;
}
__device__ __forceinline__ void unpack2(unsigned long long v, float& a, float& b) {
    asm("mov.b64 {%0, %1}, %2;" : "=f"(a), "=f"(b) : "l"(v));
}
__device__ __forceinline__ unsigned long long fma2(unsigned long long a,
                                                   unsigned long long b,
                                                   unsigned long long c) {
    unsigned long long r;
    asm("fma.rn.f32x2 %0, %1, %2, %3;" : "=l"(r) : "l"(a), "l"(b), "l"(c));
    return r;
}

// ---------------- cp.async helpers ----------------
__device__ __forceinline__ void cp16(void* smem, const void* gmem) {
    unsigned s = (unsigned)__cvta_generic_to_shared(smem);
    asm volatile("cp.async.ca.shared.global [%0], [%1], 16;" :: "r"(s), "l"(gmem));
}
__device__ __forceinline__ void cp_commit() {
    asm volatile("cp.async.commit_group;");
}
template <int N>
__device__ __forceinline__ void cp_wait() {
    asm volatile("cp.async.wait_group %0;" :: "n"(N));
}

// ---------------- kernel 1: pack candidates ----------------
__global__ void pack_kernel(const float* __restrict__ src_coords,
                            const float* __restrict__ tgt_coords) {
    int u = blockIdx.x * blockDim.x + threadIdx.x;   // 0 .. 2*NSLICE*NPAIR-1
    if (u >= 2 * NSLICE * NPAIR) return;
    int side = u >> 14;                 // NSLICE*NPAIR = 16384
    int rem  = u & 16383;
    int s    = rem >> 11;               // NPAIR = 2048
    int P    = rem & 2047;
    const float* c = side ? tgt_coords : src_coords;
    int j0 = (2 * P) * NSLICE + s;
    int j1 = j0 + NSLICE;
    float x0 = c[3 * j0], y0 = c[3 * j0 + 1], z0 = c[3 * j0 + 2];
    float x1 = c[3 * j1], y1 = c[3 * j1 + 1], z1 = c[3 * j1 + 2];
    float w0 = x0 * x0 + y0 * y0 + z0 * z0;
    float w1 = x1 * x1 + y1 * y1 + z1 * z1;
    g_pack[side][s][P][0] = make_float4(x0, x1, y0, y1);
    g_pack[side][s][P][1] = make_float4(z0, z1, w0, w1);
}

// ---------------- kernel 2: top-2 search ----------------
// Block: 256 threads = 8 warps. Warp w = slice w. Lane l = query (qbase + l).
// Per side: MQ/32 = 256 blocks. Grid = 512 blocks.
struct Top2 {
    float d1, d2;
    int   i1, i2;
};

__device__ __forceinline__ void t2_insert(Top2& t, float d, int j) {
    // precondition: d < t.d2
    if (d < t.d1) {
        t.d2 = t.d1; t.i2 = t.i1;
        t.d1 = d;    t.i1 = j;
    } else {
        t.d2 = d;    t.i2 = j;
    }
}

__global__ __launch_bounds__(256, 2)
void search_kernel(const float* __restrict__ src_sc,
                   const float* __restrict__ tgt_sc) {
    __shared__ float4 sbuf[NSLICE][2][TILE_P * 2];   // 32 KB
    __shared__ float  pd1[NSLICE * 32], pd2[NSLICE * 32];
    __shared__ int    pi1[NSLICE * 32], pi2[NSLICE * 32];

    const int side  = (blockIdx.x >= MQ / 32) ? 1 : 0;
    const int blk   = side ? (blockIdx.x - MQ / 32) : blockIdx.x;
    const int warp  = threadIdx.x >> 5;      // slice
    const int lane  = threadIdx.x & 31;      // query within block
    const int q     = blk * 32 + lane;

    const float* sc = side ? tgt_sc : src_sc;
    float qx = sc[3 * q], qy = sc[3 * q + 1], qz = sc[3 * q + 2];
    unsigned long long m2x = pack2(-2.0f * qx, -2.0f * qx);
    unsigned long long m2y = pack2(-2.0f * qy, -2.0f * qy);
    unsigned long long m2z = pack2(-2.0f * qz, -2.0f * qz);

    const float4* gsrc = &g_pack[side][warp][0][0];  // 2*NPAIR float4s

    Top2 t;
    t.d1 = 3.4e38f; t.d2 = 3.4e38f; t.i1 = 0; t.i2 = 0;

    // stage tile 0
    {
        const float4* g = gsrc;                      // tile 0: first TILE_P*2 float4
        float4* dst = &sbuf[warp][0][0];
        #pragma unroll
        for (int e = 0; e < 4; e++)
            cp16(&dst[lane + 32 * e], &g[lane + 32 * e]);
        cp_commit();
    }

    for (int tile = 0; tile < NTILE; tile++) {
        if (tile + 1 < NTILE) {
            const float4* g = gsrc + (tile + 1) * (TILE_P * 2);
            float4* dst = &sbuf[warp][(tile + 1) & 1][0];
            #pragma unroll
            for (int e = 0; e < 4; e++)
                cp16(&dst[lane + 32 * e], &g[lane + 32 * e]);
            cp_commit();
            cp_wait<1>();
        } else {
            cp_wait<0>();
        }
        __syncwarp();

        const float4* buf = &sbuf[warp][tile & 1][0];
        int jbase = (tile * TILE_P) * (2 * NSLICE) + warp;

        #pragma unroll 4
        for (int p = 0; p < TILE_P; p++) {
            ulonglong2 xy = *(const ulonglong2*)&buf[2 * p];       // (x0x1, y0y1)
            ulonglong2 zw = *(const ulonglong2*)&buf[2 * p + 1];   // (z0z1, w0w1)
            unsigned long long d = fma2(m2z, zw.x, zw.y);
            d = fma2(m2y, xy.y, d);
            d = fma2(m2x, xy.x, d);
            float dlo, dhi;
            unpack2(d, dlo, dhi);
            if (fminf(dlo, dhi) < t.d2) {            // rarely taken
                int j0 = jbase + p * (2 * NSLICE);
                if (dlo < t.d2) t2_insert(t, dlo, j0);
                if (dhi < t.d2) t2_insert(t, dhi, j0 + NSLICE);
            }
        }
        __syncwarp();
    }

    // per-thread partials -> smem
    pd1[warp * 32 + lane] = t.d1;  pd2[warp * 32 + lane] = t.d2;
    pi1[warp * 32 + lane] = t.i1;  pi2[warp * 32 + lane] = t.i2;
    __syncthreads();

    if (threadIdx.x < 32) {
        Top2 m;
        m.d1 = pd1[lane]; m.d2 = pd2[lane];
        m.i1 = pi1[lane]; m.i2 = pi2[lane];
        #pragma unroll
        for (int s = 1; s < NSLICE; s++) {
            float a = pd1[s * 32 + lane]; int ia = pi1[s * 32 + lane];
            if (a < m.d2) t2_insert(m, a, ia);
            float b = pd2[s * 32 + lane]; int ib = pi2[s * 32 + lane];
            if (b < m.d2) t2_insert(m, b, ib);
        }
        g_idx2[side][q] = m.i2;
    }
}

// ---------------- kernel 3: gather features ----------------
// One block of 64 threads per output row; each thread copies one float4.
__global__ void gather_kernel(const float* __restrict__ src_feat,
                              const float* __restrict__ tgt_feat,
                              float* __restrict__ out) {
    int row = blockIdx.x;                 // 0 .. 2*MQ-1
    int side = (row >= MQ) ? 1 : 0;
    int q = side ? (row - MQ) : row;
    const float* f = side ? tgt_feat : src_feat;
    int idx = g_idx2[side][q];
    const float4* srcp = (const float4*)(f + (size_t)idx * CF);
    float4* dstp = (float4*)(out + (size_t)row * CF);
    dstp[threadIdx.x] = srcp[threadIdx.x];
}

extern "C" void kernel_launch(void* const* d_in, const int* in_sizes, int n_in,
                              void* d_out, int out_size) {
    const float* src        = (const float*)d_in[0];   // [N, C]
    const float* tgt        = (const float*)d_in[1];   // [N, C]
    const float* src_coords = (const float*)d_in[2];   // [N, 3]
    const float* tgt_coords = (const float*)d_in[3];   // [N, 3]
    const float* src_sc     = (const float*)d_in[4];   // [M, 3]
    const float* tgt_sc     = (const float*)d_in[5];   // [M, 3]
    float* out = (float*)d_out;                        // [2*M, C]

    pack_kernel<<<(2 * NSLICE * NPAIR + 255) / 256, 256>>>(src_coords, tgt_coords);
    search_kernel<<<2 * (MQ / 32), 256>>>(src_sc, tgt_sc);
    gather_kernel<<<2 * MQ, CF / 4>>>(src, tgt, out);
}